// round 1
// baseline (speedup 1.0000x reference)
#include <cuda_runtime.h>

#define NT 128           // threads per block (one batch row per thread)
#define BTOT 32768

// ---------------- scratch (allocation-free rule: __device__ globals) --------
static __device__ float g_hq[BTOT * 4];
static __device__ float g_hp[BTOT * 4];

// ---------------- fast activations (MUFU-based, ~1e-6 accurate) -------------
__device__ __forceinline__ float sigf(float x) {
    // 1 / (1 + e^-x)
    return __fdividef(1.0f, 1.0f + __expf(-x));
}
__device__ __forceinline__ float tanhfast(float x) {
    // 1 - 2/(e^{2x}+1); saturates correctly for |x| large
    float e = __expf(2.0f * x);
    return 1.0f - __fdividef(2.0f, e + 1.0f);
}

// ---------------- shared-memory layout (floats) -----------------------------
// weights packed gate-interleaved: wih4[k][j][g], whh4[k][j][g], b4[j][g]
//   L0: Din=50 H=25   L1: Din=25 H=10   L2: Din=10 H=4
static const int OFF_WIH0 = 0;              // 50*25*4 = 5000
static const int OFF_WHH0 = 5000;           // 25*25*4 = 2500
static const int OFF_B0   = 7500;           // 100
static const int OFF_WIH1 = 7600;           // 25*10*4 = 1000
static const int OFF_WHH1 = 8600;           // 10*10*4 = 400
static const int OFF_B1   = 9000;           // 40
static const int OFF_WIH2 = 9040;           // 10*4*4 = 160
static const int OFF_WHH2 = 9200;           // 4*4*4 = 64
static const int OFF_B2   = 9264;           // 16
static const int W_TOTAL  = 9280;
// state: [elem][NT] columns, per-thread private
static const int ST_HS0 = 0;                // 25*NT
static const int ST_CS0 = 25 * NT;          // 25*NT
static const int ST_HS1 = 50 * NT;          // 10*NT
static const int ST_CS1 = 60 * NT;          // 10*NT
static const int ST_HS2 = 70 * NT;          // 4*NT
static const int ST_CS2 = 74 * NT;          // 4*NT
static const int ST_HN  = 78 * NT;          // 25*NT (shared scratch, max H)
static const int ST_TOTAL = 103 * NT;
static const int SMEM_FLOATS = W_TOTAL + ST_TOTAL;           // 22464
static const int SMEM_BYTES  = SMEM_FLOATS * 4;              // 89856 B

// ---------------- weight packers --------------------------------------------
// src Wih: [4H, DIN] row-major (torch gate order i,f,g,o).
// dst: [k][j][g] with g in {i,f,g,o}: dst[(k*H+j)*4+g] = src[(g*H+j)*DIN+k]
template <int DIN, int H>
__device__ void packw(float* dst, const float* __restrict__ src, int tid) {
    const int n = DIN * H * 4;
    for (int idx = tid; idx < n; idx += NT) {
        int g = idx & 3, jk = idx >> 2;
        int j = jk % H, k = jk / H;
        dst[idx] = src[(g * H + j) * DIN + k];
    }
}
template <int H>
__device__ void packb(float* dst, const float* __restrict__ src, int tid) {
    for (int idx = tid; idx < 4 * H; idx += NT) {
        int g = idx & 3, j = idx >> 2;
        dst[idx] = src[g * H + j];
    }
}

// ---------------- one LSTM layer step (per-thread row) ----------------------
// xget(k): input accessor (register array for L0, smem column for L1/L2)
// hs/cs/hn: smem pointers already offset by +tid; element stride NT.
template <int DIN, int H, class XF>
__device__ __forceinline__ void lstm_step(
    XF xget,
    const float* __restrict__ swih, const float* __restrict__ swhh,
    const float* __restrict__ sbias,
    float* hs, float* cs, float* hn)
{
    const float4* wih = reinterpret_cast<const float4*>(swih);
    const float4* whh = reinterpret_cast<const float4*>(swhh);
    const float4* b4  = reinterpret_cast<const float4*>(sbias);
#pragma unroll 1
    for (int j = 0; j < H; j++) {
        float4 b = b4[j];
        float ai = b.x, af = b.y, ag = b.z, ao = b.w;
#pragma unroll
        for (int k = 0; k < DIN; k++) {
            float4 w = wih[k * H + j];          // LDS.128 broadcast
            float xv = xget(k);
            ai = fmaf(xv, w.x, ai);
            af = fmaf(xv, w.y, af);
            ag = fmaf(xv, w.z, ag);
            ao = fmaf(xv, w.w, ao);
        }
#pragma unroll
        for (int k = 0; k < H; k++) {
            float4 w = whh[k * H + j];
            float hv = hs[k * NT];              // conflict-free per-lane
            ai = fmaf(hv, w.x, ai);
            af = fmaf(hv, w.y, af);
            ag = fmaf(hv, w.z, ag);
            ao = fmaf(hv, w.w, ao);
        }
        float ig = sigf(ai);
        float fg = sigf(af);
        float gg = tanhfast(ag);
        float og = sigf(ao);
        float c = fmaf(fg, cs[j * NT], ig * gg);
        cs[j * NT] = c;
        hn[j * NT] = og * tanhfast(c);
    }
#pragma unroll
    for (int j = 0; j < H; j++) hs[j * NT] = hn[j * NT];
}

// ---------------- tower kernel ----------------------------------------------
template <int T>
__global__ void __launch_bounds__(NT)
tower_kernel(const float* __restrict__ x_in,
             const float* __restrict__ Wih0, const float* __restrict__ Whh0,
             const float* __restrict__ b0,
             const float* __restrict__ Wih1, const float* __restrict__ Whh1,
             const float* __restrict__ b1,
             const float* __restrict__ Wih2, const float* __restrict__ Whh2,
             const float* __restrict__ b2,
             float* __restrict__ hout)
{
    extern __shared__ float sm[];
    const int tid = threadIdx.x;

    // pack weights into smem (gather; done once per block)
    packw<50, 25>(sm + OFF_WIH0, Wih0, tid);
    packw<25, 25>(sm + OFF_WHH0, Whh0, tid);
    packb<25>(sm + OFF_B0, b0, tid);
    packw<25, 10>(sm + OFF_WIH1, Wih1, tid);
    packw<10, 10>(sm + OFF_WHH1, Whh1, tid);
    packb<10>(sm + OFF_B1, b1, tid);
    packw<10, 4>(sm + OFF_WIH2, Wih2, tid);
    packw<4, 4>(sm + OFF_WHH2, Whh2, tid);
    packb<4>(sm + OFF_B2, b2, tid);
    __syncthreads();

    float* st  = sm + W_TOTAL;
    float* hs0 = st + ST_HS0 + tid;
    float* cs0 = st + ST_CS0 + tid;
    float* hs1 = st + ST_HS1 + tid;
    float* cs1 = st + ST_CS1 + tid;
    float* hs2 = st + ST_HS2 + tid;
    float* cs2 = st + ST_CS2 + tid;
    float* hn  = st + ST_HN  + tid;

    // zero init h, c
#pragma unroll
    for (int j = 0; j < 25; j++) { hs0[j * NT] = 0.0f; cs0[j * NT] = 0.0f; }
#pragma unroll
    for (int j = 0; j < 10; j++) { hs1[j * NT] = 0.0f; cs1[j * NT] = 0.0f; }
#pragma unroll
    for (int j = 0; j < 4; j++)  { hs2[j * NT] = 0.0f; cs2[j * NT] = 0.0f; }

    const int row = blockIdx.x * NT + tid;
    const float* xrow = x_in + (size_t)row * T * 50;

    for (int t = 0; t < T; t++) {
        // load this step's 50 inputs into registers (8B-aligned float2)
        float xr[50];
        const float2* xp = reinterpret_cast<const float2*>(xrow + t * 50);
#pragma unroll
        for (int k2 = 0; k2 < 25; k2++) {
            float2 v = __ldg(xp + k2);
            xr[2 * k2]     = v.x;
            xr[2 * k2 + 1] = v.y;
        }
        lstm_step<50, 25>([&](int k) { return xr[k]; },
                          sm + OFF_WIH0, sm + OFF_WHH0, sm + OFF_B0,
                          hs0, cs0, hn);
        lstm_step<25, 10>([&](int k) { return hs0[k * NT]; },
                          sm + OFF_WIH1, sm + OFF_WHH1, sm + OFF_B1,
                          hs1, cs1, hn);
        lstm_step<10, 4>([&](int k) { return hs1[k * NT]; },
                         sm + OFF_WIH2, sm + OFF_WHH2, sm + OFF_B2,
                         hs2, cs2, hn);
    }

#pragma unroll
    for (int j = 0; j < 4; j++) hout[row * 4 + j] = hs2[j * NT];
}

// ---------------- combine: scores -> softmax --------------------------------
__global__ void __launch_bounds__(256)
combine_kernel(const float* __restrict__ fW, const float* __restrict__ fb,
               float* __restrict__ out)
{
    int row = blockIdx.x * blockDim.x + threadIdx.x;
    float s0 = g_hq[row * 4 + 0] * g_hp[row * 4 + 0];
    float s1 = g_hq[row * 4 + 1] * g_hp[row * 4 + 1];
    float s2 = g_hq[row * 4 + 2] * g_hp[row * 4 + 2];
    float s3 = g_hq[row * 4 + 3] * g_hp[row * 4 + 3];
    float l0 = __ldg(fb + 0) + __ldg(fW + 0) * s0 + __ldg(fW + 1) * s1
                             + __ldg(fW + 2) * s2 + __ldg(fW + 3) * s3;
    float l1 = __ldg(fb + 1) + __ldg(fW + 4) * s0 + __ldg(fW + 5) * s1
                             + __ldg(fW + 6) * s2 + __ldg(fW + 7) * s3;
    float m = fmaxf(l0, l1);
    float e0 = __expf(l0 - m);
    float e1 = __expf(l1 - m);
    float inv = __fdividef(1.0f, e0 + e1);
    out[row * 2 + 0] = e0 * inv;
    out[row * 2 + 1] = e1 * inv;
}

// ---------------- launch ----------------------------------------------------
extern "C" void kernel_launch(void* const* d_in, const int* in_sizes, int n_in,
                              void* d_out, int out_size)
{
    const float* q  = (const float*)d_in[0];
    const float* p  = (const float*)d_in[1];
    const float* qw[9];
    const float* pw[9];
    for (int i = 0; i < 9; i++) qw[i] = (const float*)d_in[2 + i];
    for (int i = 0; i < 9; i++) pw[i] = (const float*)d_in[11 + i];
    const float* fW = (const float*)d_in[20];
    const float* fb = (const float*)d_in[21];
    float* out = (float*)d_out;

    float *hq, *hp;
    cudaGetSymbolAddress((void**)&hq, g_hq);
    cudaGetSymbolAddress((void**)&hp, g_hp);

    cudaFuncSetAttribute(tower_kernel<12>,
                         cudaFuncAttributeMaxDynamicSharedMemorySize, SMEM_BYTES);
    cudaFuncSetAttribute(tower_kernel<50>,
                         cudaFuncAttributeMaxDynamicSharedMemorySize, SMEM_BYTES);

    tower_kernel<12><<<BTOT / NT, NT, SMEM_BYTES>>>(
        q, qw[0], qw[1], qw[2], qw[3], qw[4], qw[5], qw[6], qw[7], qw[8], hq);
    tower_kernel<50><<<BTOT / NT, NT, SMEM_BYTES>>>(
        p, pw[0], pw[1], pw[2], pw[3], pw[4], pw[5], pw[6], pw[7], pw[8], hp);
    combine_kernel<<<BTOT / 256, 256>>>(fW, fb, out);
}

// round 7
// speedup vs baseline: 1.2490x; 1.2490x over previous
#include <cuda_runtime.h>

#define NT 128           // threads per block (one batch row per thread)
#define BTOT 32768
typedef unsigned long long u64;

// ---------------- scratch (allocation-free rule: __device__ globals) --------
static __device__ float g_hq[BTOT * 4];
static __device__ float g_hp[BTOT * 4];

// ---------------- f32x2 helpers ---------------------------------------------
__device__ __forceinline__ u64 splat2(float x) {
    u64 r;
    asm("mov.b64 %0, {%1, %1};" : "=l"(r) : "f"(x));
    return r;
}
__device__ __forceinline__ u64 fma2(u64 a, u64 b, u64 c) {
    u64 d;
    asm("fma.rn.f32x2 %0, %1, %2, %3;" : "=l"(d) : "l"(a), "l"(b), "l"(c));
    return d;
}
__device__ __forceinline__ void unpack2(u64 v, float& lo, float& hi) {
    asm("mov.b64 {%0, %1}, %2;" : "=f"(lo), "=f"(hi) : "l"(v));
}

// ---------------- fast activations (MUFU-based, ~1e-6 accurate) -------------
__device__ __forceinline__ float sigf(float x) {
    return __fdividef(1.0f, 1.0f + __expf(-x));
}
__device__ __forceinline__ float tanhfast(float x) {
    float e = __expf(2.0f * x);
    return 1.0f - __fdividef(2.0f, e + 1.0f);
}

// ---------------- shared-memory layout (floats) -----------------------------
// weights gate-interleaved: w4[k][j][{i,f,g,o}]  (all offsets 16B-aligned)
static const int OFF_WIH0 = 0;              // 50*25*4 = 5000
static const int OFF_WHH0 = 5000;           // 25*25*4 = 2500
static const int OFF_B0   = 7500;           // 100
static const int OFF_WIH1 = 7600;           // 25*10*4 = 1000
static const int OFF_WHH1 = 8600;           // 10*10*4 = 400
static const int OFF_B1   = 9000;           // 40
static const int OFF_WIH2 = 9040;           // 10*4*4 = 160
static const int OFF_WHH2 = 9200;           // 4*4*4 = 64
static const int OFF_B2   = 9264;           // 16
static const int W_TOTAL  = 9280;
// per-thread state columns [elem][NT]
static const int ST_HS0 = 0;                // 25*NT
static const int ST_CS0 = 25 * NT;
static const int ST_HS1 = 50 * NT;          // 10*NT
static const int ST_CS1 = 60 * NT;
static const int ST_HS2 = 70 * NT;          // 4*NT
static const int ST_CS2 = 74 * NT;
static const int ST_TOTAL = 78 * NT;
static const int SMEM_BYTES = (W_TOTAL + ST_TOTAL) * 4;     // 77,056 B -> 2 blocks/SM

// ---------------- weight packers --------------------------------------------
// src Wih: [4H, DIN] row-major (torch gate order i,f,g,o).
// dst[(k*H+j)*4+g] = src[(g*H+j)*DIN+k]
template <int DIN, int H>
__device__ void packw(float* dst, const float* __restrict__ src, int tid) {
    const int n = DIN * H * 4;
    for (int idx = tid; idx < n; idx += NT) {
        int g = idx & 3, jk = idx >> 2;
        int j = jk % H, k = jk / H;
        dst[idx] = src[(g * H + j) * DIN + k];
    }
}
template <int H>
__device__ void packb(float* dst, const float* __restrict__ src, int tid) {
    for (int idx = tid; idx < 4 * H; idx += NT) {
        int g = idx & 3, j = idx >> 2;
        dst[idx] = src[g * H + j];
    }
}

// ---------------- one LSTM layer step, gate-packed f32x2 --------------------
// xs: DIN splatted inputs (registers). hsp: scratch for H splatted old-h.
// hs/cs: smem state columns (pointer already +tid, stride NT).
template <int DIN, int H>
__device__ __forceinline__ void step2(
    const u64* xs,
    const float* swih, const float* swhh, const float* sbias,
    float* hs, float* cs, u64* hsp)
{
#pragma unroll
    for (int k = 0; k < H; k++) hsp[k] = splat2(hs[k * NT]);

    const ulonglong2* wih = reinterpret_cast<const ulonglong2*>(swih);
    const ulonglong2* whh = reinterpret_cast<const ulonglong2*>(swhh);
    const ulonglong2* bb  = reinterpret_cast<const ulonglong2*>(sbias);

#pragma unroll 1
    for (int j = 0; j < H; j++) {
        ulonglong2 b = bb[j];
        u64 a01 = b.x;    // {acc_i, acc_f}
        u64 a23 = b.y;    // {acc_g, acc_o}
#pragma unroll
        for (int k = 0; k < DIN; k++) {
            ulonglong2 w = wih[k * H + j];      // one LDS.128 -> both pairs
            a01 = fma2(xs[k], w.x, a01);
            a23 = fma2(xs[k], w.y, a23);
        }
#pragma unroll
        for (int k = 0; k < H; k++) {
            ulonglong2 w = whh[k * H + j];
            a01 = fma2(hsp[k], w.x, a01);
            a23 = fma2(hsp[k], w.y, a23);
        }
        float ai, af, ag, ao;
        unpack2(a01, ai, af);
        unpack2(a23, ag, ao);
        float c = fmaf(sigf(af), cs[j * NT], sigf(ai) * tanhfast(ag));
        cs[j * NT] = c;
        hs[j * NT] = sigf(ao) * tanhfast(c);    // old h lives in hsp regs: safe
    }
}

// ---------------- tower body ------------------------------------------------
template <int T>
__device__ __forceinline__ void run_tower(
    const float* __restrict__ x_in,
    const float* __restrict__ Wih0, const float* __restrict__ Whh0,
    const float* __restrict__ b0,
    const float* __restrict__ Wih1, const float* __restrict__ Whh1,
    const float* __restrict__ b1,
    const float* __restrict__ Wih2, const float* __restrict__ Whh2,
    const float* __restrict__ b2,
    float* __restrict__ hout, int blockbase, float* sm)
{
    const int tid = threadIdx.x;

    packw<50, 25>(sm + OFF_WIH0, Wih0, tid);
    packw<25, 25>(sm + OFF_WHH0, Whh0, tid);
    packb<25>(sm + OFF_B0, b0, tid);
    packw<25, 10>(sm + OFF_WIH1, Wih1, tid);
    packw<10, 10>(sm + OFF_WHH1, Whh1, tid);
    packb<10>(sm + OFF_B1, b1, tid);
    packw<10, 4>(sm + OFF_WIH2, Wih2, tid);
    packw<4, 4>(sm + OFF_WHH2, Whh2, tid);
    packb<4>(sm + OFF_B2, b2, tid);
    __syncthreads();

    float* st  = sm + W_TOTAL;
    float* hs0 = st + ST_HS0 + tid;
    float* cs0 = st + ST_CS0 + tid;
    float* hs1 = st + ST_HS1 + tid;
    float* cs1 = st + ST_CS1 + tid;
    float* hs2 = st + ST_HS2 + tid;
    float* cs2 = st + ST_CS2 + tid;

#pragma unroll
    for (int j = 0; j < 25; j++) { hs0[j * NT] = 0.0f; cs0[j * NT] = 0.0f; }
#pragma unroll
    for (int j = 0; j < 10; j++) { hs1[j * NT] = 0.0f; cs1[j * NT] = 0.0f; }
#pragma unroll
    for (int j = 0; j < 4; j++)  { hs2[j * NT] = 0.0f; cs2[j * NT] = 0.0f; }

    const int row = blockbase * NT + tid;
    const float* xrow = x_in + (size_t)row * T * 50;

    u64 xs[50];
    u64 hsp[25];

    for (int t = 0; t < T; t++) {
        const float2* xp = reinterpret_cast<const float2*>(xrow + t * 50);
#pragma unroll
        for (int k2 = 0; k2 < 25; k2++) {
            float2 v = __ldg(xp + k2);
            xs[2 * k2]     = splat2(v.x);
            xs[2 * k2 + 1] = splat2(v.y);
        }
        step2<50, 25>(xs, sm + OFF_WIH0, sm + OFF_WHH0, sm + OFF_B0,
                      hs0, cs0, hsp);
#pragma unroll
        for (int k = 0; k < 25; k++) xs[k] = splat2(hs0[k * NT]);
        step2<25, 10>(xs, sm + OFF_WIH1, sm + OFF_WHH1, sm + OFF_B1,
                      hs1, cs1, hsp);
#pragma unroll
        for (int k = 0; k < 10; k++) xs[k] = splat2(hs1[k * NT]);
        step2<10, 4>(xs, sm + OFF_WIH2, sm + OFF_WHH2, sm + OFF_B2,
                     hs2, cs2, hsp);
    }

#pragma unroll
    for (int j = 0; j < 4; j++) hout[row * 4 + j] = hs2[j * NT];
}

// ---------------- merged dual-tower kernel ----------------------------------
__global__ void __launch_bounds__(NT)
towers_kernel(
    const float* __restrict__ q, const float* __restrict__ p,
    const float* qa0, const float* qa1, const float* qa2,
    const float* qa3, const float* qa4, const float* qa5,
    const float* qa6, const float* qa7, const float* qa8,
    const float* pa0, const float* pa1, const float* pa2,
    const float* pa3, const float* pa4, const float* pa5,
    const float* pa6, const float* pa7, const float* pa8)
{
    extern __shared__ float sm[];
    if (blockIdx.x < BTOT / NT) {
        // p tower first (T=50, long blocks start in wave 1)
        run_tower<50>(p, pa0, pa1, pa2, pa3, pa4, pa5, pa6, pa7, pa8,
                      g_hp, blockIdx.x, sm);
    } else {
        run_tower<12>(q, qa0, qa1, qa2, qa3, qa4, qa5, qa6, qa7, qa8,
                      g_hq, blockIdx.x - BTOT / NT, sm);
    }
}

// ---------------- combine: scores -> softmax --------------------------------
__global__ void __launch_bounds__(256)
combine_kernel(const float* __restrict__ fW, const float* __restrict__ fb,
               float* __restrict__ out)
{
    int row = blockIdx.x * blockDim.x + threadIdx.x;
    float s0 = g_hq[row * 4 + 0] * g_hp[row * 4 + 0];
    float s1 = g_hq[row * 4 + 1] * g_hp[row * 4 + 1];
    float s2 = g_hq[row * 4 + 2] * g_hp[row * 4 + 2];
    float s3 = g_hq[row * 4 + 3] * g_hp[row * 4 + 3];
    float l0 = __ldg(fb + 0) + __ldg(fW + 0) * s0 + __ldg(fW + 1) * s1
                             + __ldg(fW + 2) * s2 + __ldg(fW + 3) * s3;
    float l1 = __ldg(fb + 1) + __ldg(fW + 4) * s0 + __ldg(fW + 5) * s1
                             + __ldg(fW + 6) * s2 + __ldg(fW + 7) * s3;
    float m = fmaxf(l0, l1);
    float e0 = __expf(l0 - m);
    float e1 = __expf(l1 - m);
    float inv = __fdividef(1.0f, e0 + e1);
    out[row * 2 + 0] = e0 * inv;
    out[row * 2 + 1] = e1 * inv;
}

// ---------------- launch ----------------------------------------------------
extern "C" void kernel_launch(void* const* d_in, const int* in_sizes, int n_in,
                              void* d_out, int out_size)
{
    const float* q  = (const float*)d_in[0];
    const float* p  = (const float*)d_in[1];
    const float* qw[9];
    const float* pw[9];
    for (int i = 0; i < 9; i++) qw[i] = (const float*)d_in[2 + i];
    for (int i = 0; i < 9; i++) pw[i] = (const float*)d_in[11 + i];
    const float* fW = (const float*)d_in[20];
    const float* fb = (const float*)d_in[21];
    float* out = (float*)d_out;

    cudaFuncSetAttribute(towers_kernel,
                         cudaFuncAttributeMaxDynamicSharedMemorySize, SMEM_BYTES);

    towers_kernel<<<2 * (BTOT / NT), NT, SMEM_BYTES>>>(
        q, p,
        qw[0], qw[1], qw[2], qw[3], qw[4], qw[5], qw[6], qw[7], qw[8],
        pw[0], pw[1], pw[2], pw[3], pw[4], pw[5], pw[6], pw[7], pw[8]);
    combine_kernel<<<BTOT / 256, 256>>>(fW, fb, out);
}